// round 5
// baseline (speedup 1.0000x reference)
#include <cuda_runtime.h>

// Problem constants (fixed by the reference: B=4, C=32, H=64, W=64, NW=64)
#define NW_   64
#define HW_   4096
#define C_    32
#define B_    4
#define TPB   256           // threads per block
#define PPT   4             // pixels per thread
#define TILES (HW_ / (TPB * PPT))   // 4 tiles per (b,c) image

__device__ __forceinline__ float ex2f(float x) {
    float y;
    asm("ex2.approx.f32 %0, %1;" : "=f"(y) : "f"(x));
    return y;
}

__global__ __launch_bounds__(TPB) void cplx_rbf_kernel(
    const float* __restrict__ x_real, const float* __restrict__ x_imag,
    const float* __restrict__ w_real, const float* __restrict__ w_imag,
    const float* __restrict__ b_real, const float* __restrict__ b_imag,
    const float* __restrict__ mu_real, const float* __restrict__ mu_imag,
    const float* __restrict__ stddev,
    float* __restrict__ out)
{
    __shared__ float4 s_coef[NW_];     // {A, B, C, D} per center
    __shared__ float  s_w[2 * NW_];    // [0:64) w_real[c,:], [64:128) w_imag[c,:]

    const int bc   = blockIdx.x >> 2;          // (b*C + c), TILES == 4
    const int tile = blockIdx.x & (TILES - 1);
    const int c    = bc & (C_ - 1);

    const int t = threadIdx.x;
    if (t < NW_) {
        const float mur = mu_real[t];
        const float mui = mu_imag[t];
        // A = -log2(e) / (2*sigma); fold log2e so exp() becomes a single EX2
        const float A = -0.72134752044448169f / stddev[t];
        s_coef[t] = make_float4(A, -2.0f * A * mur, -2.0f * A * mui,
                                A * (mur * mur + mui * mui));
        s_w[t]        = w_real[c * NW_ + t];
        s_w[NW_ + t]  = w_imag[c * NW_ + t];
    }
    __syncthreads();

    const int p0   = tile * (TPB * PPT) + t * PPT;   // 4 consecutive pixels
    const int gidx = bc * HW_ + p0;                  // 16B-aligned

    const float4 xr = *reinterpret_cast<const float4*>(x_real + gidx);
    const float4 xi = *reinterpret_cast<const float4*>(x_imag + gidx);

    // s = |x|^2 per pixel (computed once, reused across all 64 centers)
    const float s0 = fmaf(xr.x, xr.x, xi.x * xi.x);
    const float s1 = fmaf(xr.y, xr.y, xi.y * xi.y);
    const float s2 = fmaf(xr.z, xr.z, xi.z * xi.z);
    const float s3 = fmaf(xr.w, xr.w, xi.w * xi.w);

    float ar0 = 0.f, ar1 = 0.f, ar2 = 0.f, ar3 = 0.f;
    float ai0 = 0.f, ai1 = 0.f, ai2 = 0.f, ai3 = 0.f;

#pragma unroll 8
    for (int w = 0; w < NW_; ++w) {
        const float4 cf = s_coef[w];
        const float  wr = s_w[w];
        const float  wi = s_w[NW_ + w];

        // arg = A*s + B*xr + C*xi + D  (3 FFMA), then one EX2 per pixel
        const float e0 = ex2f(fmaf(cf.x, s0, fmaf(cf.y, xr.x, fmaf(cf.z, xi.x, cf.w))));
        const float e1 = ex2f(fmaf(cf.x, s1, fmaf(cf.y, xr.y, fmaf(cf.z, xi.y, cf.w))));
        const float e2 = ex2f(fmaf(cf.x, s2, fmaf(cf.y, xr.z, fmaf(cf.z, xi.z, cf.w))));
        const float e3 = ex2f(fmaf(cf.x, s3, fmaf(cf.y, xr.w, fmaf(cf.z, xi.w, cf.w))));

        ar0 = fmaf(e0, wr, ar0);  ai0 = fmaf(e0, wi, ai0);
        ar1 = fmaf(e1, wr, ar1);  ai1 = fmaf(e1, wi, ai1);
        ar2 = fmaf(e2, wr, ar2);  ai2 = fmaf(e2, wi, ai2);
        ar3 = fmaf(e3, wr, ar3);  ai3 = fmaf(e3, wi, ai3);
    }

    const float br = b_real[c];
    const float bi = b_imag[c];

    // Output layout (B,C,H,W,2): real/imag interleaved -> two float4 stores (32B)
    float4* op = reinterpret_cast<float4*>(out + 2 * gidx);
    op[0] = make_float4(ar0 + br, ai0 + bi, ar1 + br, ai1 + bi);
    op[1] = make_float4(ar2 + br, ai2 + bi, ar3 + br, ai3 + bi);
}

extern "C" void kernel_launch(void* const* d_in, const int* in_sizes, int n_in,
                              void* d_out, int out_size)
{
    const float* x_real  = (const float*)d_in[0];
    const float* x_imag  = (const float*)d_in[1];
    const float* w_real  = (const float*)d_in[2];
    const float* w_imag  = (const float*)d_in[3];
    const float* b_real  = (const float*)d_in[4];
    const float* b_imag  = (const float*)d_in[5];
    const float* mu_real = (const float*)d_in[6];
    const float* mu_imag = (const float*)d_in[7];
    const float* stddev  = (const float*)d_in[8];
    float* out = (float*)d_out;

    const int grid = B_ * C_ * TILES;   // 512 blocks
    cplx_rbf_kernel<<<grid, TPB>>>(x_real, x_imag, w_real, w_imag,
                                   b_real, b_imag, mu_real, mu_imag,
                                   stddev, out);
}